// round 1
// baseline (speedup 1.0000x reference)
#include <cuda_runtime.h>
#include <math.h>

// Problem constants (fixed shapes from reference)
#define D_MODEL   1024
#define N_HEADS   16
#define HEAD_DIM  64
#define SEQ       2048
#define BATCH     2
#define M_TOT     (BATCH * SEQ)      // 4096 rows for all projections

// ---------------------------------------------------------------------------
// Scratch (device globals — no allocations allowed)
// Q/K/V stored as [b][h][s][d]; AO stored as [b][s][h*64+d] = [4096][1024]
// ---------------------------------------------------------------------------
__device__ float g_Q [BATCH * N_HEADS * SEQ * HEAD_DIM];
__device__ float g_K [BATCH * N_HEADS * SEQ * HEAD_DIM];
__device__ float g_V [BATCH * N_HEADS * SEQ * HEAD_DIM];
__device__ float g_AO[M_TOT * D_MODEL];

// ---------------------------------------------------------------------------
// GEMM: C[m,n] = sum_k A[m,k] * W[n,k] + bias[n]
// A: [4096,1024] row-major, W: [1024,1024] row-major (we multiply by W^T).
// 128x128 block tile, BK=8, 256 threads, 8x8 per thread, register prefetch.
// MODE 0: write plain row-major to C param (final output)
//         and read A from g_AO (attention output scratch).
// MODE 1/2/3: read A param (x), write [b][h][s][d] scatter to g_Q/g_K/g_V.
// ---------------------------------------------------------------------------
template <int MODE>
__global__ void __launch_bounds__(256)
gemm_nt_kernel(const float* __restrict__ A,
               const float* __restrict__ W,
               const float* __restrict__ bias,
               float* __restrict__ C)
{
    const int K = 1024;
    const int N = 1024;

    __shared__ float As[8][128];
    __shared__ float Ws[8][128];

    const float* Asrc = (MODE == 0) ? g_AO : A;

    int tid  = threadIdx.x;
    int bm   = blockIdx.y * 128;
    int bn   = blockIdx.x * 128;

    int lrow = tid >> 1;           // 0..127
    int lcol = (tid & 1) << 2;     // 0 or 4

    const float* Ap = Asrc + (size_t)(bm + lrow) * K + lcol;
    const float* Wp = W    + (size_t)(bn + lrow) * K + lcol;

    int tx = tid & 15;             // n-tile index
    int ty = tid >> 4;             // m-tile index

    float acc[8][8];
    #pragma unroll
    for (int i = 0; i < 8; i++)
        #pragma unroll
        for (int j = 0; j < 8; j++)
            acc[i][j] = 0.0f;

    float4 areg = *reinterpret_cast<const float4*>(Ap);
    float4 wreg = *reinterpret_cast<const float4*>(Wp);

    for (int kt = 0; kt < K; kt += 8) {
        // commit current prefetch regs to smem (transposed: [k][row])
        As[lcol + 0][lrow] = areg.x;
        As[lcol + 1][lrow] = areg.y;
        As[lcol + 2][lrow] = areg.z;
        As[lcol + 3][lrow] = areg.w;
        Ws[lcol + 0][lrow] = wreg.x;
        Ws[lcol + 1][lrow] = wreg.y;
        Ws[lcol + 2][lrow] = wreg.z;
        Ws[lcol + 3][lrow] = wreg.w;
        __syncthreads();

        // prefetch next k-tile (latency hidden under FFMA below)
        if (kt + 8 < K) {
            areg = *reinterpret_cast<const float4*>(Ap + kt + 8);
            wreg = *reinterpret_cast<const float4*>(Wp + kt + 8);
        }

        #pragma unroll
        for (int k = 0; k < 8; k++) {
            float4 a0 = *reinterpret_cast<const float4*>(&As[k][ty * 8]);
            float4 a1 = *reinterpret_cast<const float4*>(&As[k][ty * 8 + 4]);
            float4 w0 = *reinterpret_cast<const float4*>(&Ws[k][tx * 8]);
            float4 w1 = *reinterpret_cast<const float4*>(&Ws[k][tx * 8 + 4]);
            float av[8] = {a0.x, a0.y, a0.z, a0.w, a1.x, a1.y, a1.z, a1.w};
            float wv[8] = {w0.x, w0.y, w0.z, w0.w, w1.x, w1.y, w1.z, w1.w};
            #pragma unroll
            for (int i = 0; i < 8; i++)
                #pragma unroll
                for (int j = 0; j < 8; j++)
                    acc[i][j] += av[i] * wv[j];
        }
        __syncthreads();
    }

    // epilogue
    #pragma unroll
    for (int i = 0; i < 8; i++) {
        int m = bm + ty * 8 + i;
        #pragma unroll
        for (int j = 0; j < 8; j++) {
            int n = bn + tx * 8 + j;
            float v = acc[i][j] + bias[n];
            if (MODE == 0) {
                C[(size_t)m * N + n] = v;
            } else {
                // scatter to [b][h][s][d]
                int b = m >> 11;        // m / 2048
                int s = m & 2047;
                int h = n >> 6;         // n / 64
                int d = n & 63;
                size_t idx = ((size_t)((b << 4) + h) * SEQ + s) * HEAD_DIM + d;
                if (MODE == 1) g_Q[idx] = v;
                else if (MODE == 2) g_K[idx] = v;
                else g_V[idx] = v;
            }
        }
    }
}

// ---------------------------------------------------------------------------
// Flash attention, fp32. Block = (q-tile 64, head, batch). 256 threads.
// Online softmax over kv tiles of 64. Q pre-scaled by 1/sqrt(64).
// Dynamic smem layout:
//   Qs [64][68]  (k-major: [d][q])
//   Ks [64][68]  (k-major: [d][j])
//   Ss [64][68]  (scores [q][j])
//   Vs [64][64]  (natural [j][d])
// ---------------------------------------------------------------------------
#define QS(k, q) smQ[(k) * 68 + (q)]
#define KS(k, j) smK[(k) * 68 + (j)]
#define SS(q, j) smS[(q) * 68 + (j)]
#define VS(j, d) smV[(j) * 64 + (d)]

#define ATTN_SMEM_FLOATS (3 * 64 * 68 + 64 * 64)

__global__ void __launch_bounds__(256)
attn_kernel(const int* __restrict__ mask)
{
    extern __shared__ float sm[];
    float* smQ = sm;
    float* smK = smQ + 64 * 68;
    float* smS = smK + 64 * 68;
    float* smV = smS + 64 * 68;

    __shared__ float m_s[64];
    __shared__ float l_s[64];
    __shared__ float alpha_s[64];
    __shared__ int   msk_s[64];

    int qb = blockIdx.x;     // q tile (0..31)
    int h  = blockIdx.y;     // head
    int b  = blockIdx.z;     // batch
    int tid = threadIdx.x;

    const float* Qh = g_Q + ((size_t)(b * N_HEADS + h) * SEQ + qb * 64) * HEAD_DIM;
    const float* Kh = g_K + ((size_t)(b * N_HEADS + h) * SEQ) * HEAD_DIM;
    const float* Vh = g_V + ((size_t)(b * N_HEADS + h) * SEQ) * HEAD_DIM;
    const int* maskb = mask + (size_t)b * SEQ;

    // load + transpose + pre-scale Q tile
    for (int i = tid; i < 64 * 64; i += 256) {
        int q = i >> 6, d = i & 63;
        QS(d, q) = Qh[q * 64 + d] * 0.125f;    // 1/sqrt(HEAD_DIM)
    }
    if (tid < 64) { m_s[tid] = -INFINITY; l_s[tid] = 0.0f; }

    int tx = tid & 15;   // j / d group
    int ty = tid >> 4;   // q group
    float o[4][4];
    #pragma unroll
    for (int i = 0; i < 4; i++)
        #pragma unroll
        for (int j = 0; j < 4; j++)
            o[i][j] = 0.0f;

    for (int t = 0; t < SEQ / 64; t++) {
        __syncthreads();   // smem reuse barrier (also covers Q load on t=0)

        // load K (transposed) and V (natural) tiles — coalesced on d
        for (int i = tid; i < 64 * 64; i += 256) {
            int j = i >> 6, d = i & 63;
            float kv = Kh[(size_t)(t * 64 + j) * 64 + d];
            float vv = Vh[(size_t)(t * 64 + j) * 64 + d];
            KS(d, j) = kv;
            VS(j, d) = vv;
        }
        if (tid < 64) msk_s[tid] = maskb[t * 64 + tid];
        __syncthreads();

        // S = Q K^T (scaled), 4x4 per thread
        float sacc[4][4];
        #pragma unroll
        for (int i = 0; i < 4; i++)
            #pragma unroll
            for (int j = 0; j < 4; j++)
                sacc[i][j] = 0.0f;

        #pragma unroll 8
        for (int k = 0; k < 64; k++) {
            float4 qv = *reinterpret_cast<const float4*>(&QS(k, ty * 4));
            float4 kv = *reinterpret_cast<const float4*>(&KS(k, tx * 4));
            float qa[4] = {qv.x, qv.y, qv.z, qv.w};
            float ka[4] = {kv.x, kv.y, kv.z, kv.w};
            #pragma unroll
            for (int i = 0; i < 4; i++)
                #pragma unroll
                for (int j = 0; j < 4; j++)
                    sacc[i][j] += qa[i] * ka[j];
        }

        // store scores with mask
        #pragma unroll
        for (int i = 0; i < 4; i++)
            #pragma unroll
            for (int j = 0; j < 4; j++) {
                int jj = tx * 4 + j;
                SS(ty * 4 + i, jj) = (msk_s[jj] != 0) ? sacc[i][j] : -1.0e10f;
            }
        __syncthreads();

        // online softmax: 4 threads per row (same warp, lanes r*4+seg)
        {
            int r = tid >> 2;
            int seg = tid & 3;
            float* Srow = &SS(r, 0);
            float lm = -INFINITY;
            #pragma unroll
            for (int c = 0; c < 16; c++)
                lm = fmaxf(lm, Srow[seg * 16 + c]);
            lm = fmaxf(lm, __shfl_xor_sync(0xffffffffu, lm, 1));
            lm = fmaxf(lm, __shfl_xor_sync(0xffffffffu, lm, 2));

            float m_old = m_s[r];
            float m_new = fmaxf(m_old, lm);

            float lsum = 0.0f;
            #pragma unroll
            for (int c = 0; c < 16; c++) {
                float p = __expf(Srow[seg * 16 + c] - m_new);
                Srow[seg * 16 + c] = p;
                lsum += p;
            }
            lsum += __shfl_xor_sync(0xffffffffu, lsum, 1);
            lsum += __shfl_xor_sync(0xffffffffu, lsum, 2);

            if (seg == 0) {
                float a = __expf(m_old - m_new);   // exp(-inf)=0 on first tile
                alpha_s[r] = a;
                l_s[r] = l_s[r] * a + lsum;
                m_s[r] = m_new;
            }
        }
        __syncthreads();

        // O = O*alpha + P @ V
        float al[4];
        #pragma unroll
        for (int i = 0; i < 4; i++) al[i] = alpha_s[ty * 4 + i];
        #pragma unroll
        for (int i = 0; i < 4; i++)
            #pragma unroll
            for (int j = 0; j < 4; j++)
                o[i][j] *= al[i];

        #pragma unroll 8
        for (int j = 0; j < 64; j++) {
            float4 vv = *reinterpret_cast<const float4*>(&VS(j, tx * 4));
            float va[4] = {vv.x, vv.y, vv.z, vv.w};
            float p0 = SS(ty * 4 + 0, j);
            float p1 = SS(ty * 4 + 1, j);
            float p2 = SS(ty * 4 + 2, j);
            float p3 = SS(ty * 4 + 3, j);
            #pragma unroll
            for (int jj = 0; jj < 4; jj++) {
                o[0][jj] += p0 * va[jj];
                o[1][jj] += p1 * va[jj];
                o[2][jj] += p2 * va[jj];
                o[3][jj] += p3 * va[jj];
            }
        }
    }

    // finalize: divide by l, write to [b][s][h*64+d]
    #pragma unroll
    for (int i = 0; i < 4; i++) {
        int q = qb * 64 + ty * 4 + i;
        float invl = 1.0f / l_s[ty * 4 + i];
        #pragma unroll
        for (int j = 0; j < 4; j++) {
            int d = tx * 4 + j;
            g_AO[((size_t)b * SEQ + q) * D_MODEL + h * HEAD_DIM + d] = o[i][j] * invl;
        }
    }
}

// ---------------------------------------------------------------------------
// Launcher
// ---------------------------------------------------------------------------
extern "C" void kernel_launch(void* const* d_in, const int* in_sizes, int n_in,
                              void* d_out, int out_size)
{
    const float* x    = (const float*)d_in[0];
    const int*   mask = (const int*)  d_in[1];
    const float* Wq   = (const float*)d_in[2];
    const float* bq   = (const float*)d_in[3];
    const float* Wk   = (const float*)d_in[4];
    const float* bk   = (const float*)d_in[5];
    const float* Wv   = (const float*)d_in[6];
    const float* bv   = (const float*)d_in[7];
    const float* Wo   = (const float*)d_in[8];
    const float* bo   = (const float*)d_in[9];
    float* out = (float*)d_out;

    dim3 ggrid(D_MODEL / 128, M_TOT / 128);   // (8, 32)

    // Q/K/V projections ([b][h][s][d] scatter into scratch)
    gemm_nt_kernel<1><<<ggrid, 256>>>(x, Wq, bq, nullptr);
    gemm_nt_kernel<2><<<ggrid, 256>>>(x, Wk, bk, nullptr);
    gemm_nt_kernel<3><<<ggrid, 256>>>(x, Wv, bv, nullptr);

    // Flash attention
    const int attn_smem = ATTN_SMEM_FLOATS * (int)sizeof(float);  // ~68.6 KB
    cudaFuncSetAttribute(attn_kernel, cudaFuncAttributeMaxDynamicSharedMemorySize,
                         attn_smem);
    attn_kernel<<<dim3(SEQ / 64, N_HEADS, BATCH), 256, attn_smem>>>(mask);

    // Output projection (reads g_AO internally)
    gemm_nt_kernel<0><<<ggrid, 256>>>(nullptr, Wo, bo, out);
}

// round 3
// speedup vs baseline: 1.4277x; 1.4277x over previous
#include <cuda_runtime.h>
#include <cuda_bf16.h>
#include <math.h>
#include <stdint.h>

// Problem constants
#define D_MODEL   1024
#define N_HEADS   16
#define HEAD_DIM  64
#define SEQ       2048
#define BATCH     2
#define M_TOT     (BATCH * SEQ)      // 4096

// ---------------------------------------------------------------------------
// Scratch (device globals — no allocations allowed)
// ---------------------------------------------------------------------------
__device__ __align__(128) float g_Q [BATCH * N_HEADS * SEQ * HEAD_DIM];
__device__ __align__(128) float g_K [BATCH * N_HEADS * SEQ * HEAD_DIM];
__device__ __align__(128) float g_V [BATCH * N_HEADS * SEQ * HEAD_DIM];
__device__ __align__(128) float g_AO[M_TOT * D_MODEL];

// bf16 hi/lo splits
__device__ __align__(128) __nv_bfloat16 g_xhi [M_TOT * D_MODEL];
__device__ __align__(128) __nv_bfloat16 g_xlo [M_TOT * D_MODEL];
__device__ __align__(128) __nv_bfloat16 g_aohi[M_TOT * D_MODEL];
__device__ __align__(128) __nv_bfloat16 g_aolo[M_TOT * D_MODEL];
__device__ __align__(128) __nv_bfloat16 g_wqhi[D_MODEL * D_MODEL];
__device__ __align__(128) __nv_bfloat16 g_wqlo[D_MODEL * D_MODEL];
__device__ __align__(128) __nv_bfloat16 g_wkhi[D_MODEL * D_MODEL];
__device__ __align__(128) __nv_bfloat16 g_wklo[D_MODEL * D_MODEL];
__device__ __align__(128) __nv_bfloat16 g_wvhi[D_MODEL * D_MODEL];
__device__ __align__(128) __nv_bfloat16 g_wvlo[D_MODEL * D_MODEL];
__device__ __align__(128) __nv_bfloat16 g_wohi[D_MODEL * D_MODEL];
__device__ __align__(128) __nv_bfloat16 g_wolo[D_MODEL * D_MODEL];

// ---------------------------------------------------------------------------
// Base-ISA helpers (no "a"-feature instructions: harness targets compute_103)
// ---------------------------------------------------------------------------
__device__ __forceinline__ uint32_t smem_u32(const void* p) {
    uint32_t a;
    asm("{ .reg .u64 t; cvta.to.shared.u64 t, %1; cvt.u32.u64 %0, t; }"
        : "=r"(a) : "l"(p));
    return a;
}

__device__ __forceinline__ void ldsm_x4(uint32_t* r, uint32_t addr) {
    asm volatile("ldmatrix.sync.aligned.m8n8.x4.shared.b16 {%0,%1,%2,%3}, [%4];"
                 : "=r"(r[0]), "=r"(r[1]), "=r"(r[2]), "=r"(r[3]) : "r"(addr));
}

__device__ __forceinline__ void mma16816(float* c, const uint32_t* a,
                                         const uint32_t* b) {
    asm volatile(
        "mma.sync.aligned.m16n8k16.row.col.f32.bf16.bf16.f32 "
        "{%0,%1,%2,%3}, {%4,%5,%6,%7}, {%8,%9}, {%0,%1,%2,%3};"
        : "+f"(c[0]), "+f"(c[1]), "+f"(c[2]), "+f"(c[3])
        : "r"(a[0]), "r"(a[1]), "r"(a[2]), "r"(a[3]), "r"(b[0]), "r"(b[1]));
}

#define CP_ASYNC16(dst, src) \
    asm volatile("cp.async.cg.shared.global [%0], [%1], 16;" \
        :: "r"(dst), "l"(src))
#define CP_COMMIT() asm volatile("cp.async.commit_group;" ::: "memory")
#define CP_WAIT1()  asm volatile("cp.async.wait_group 1;" ::: "memory")
#define CP_WAIT0()  asm volatile("cp.async.wait_group 0;" ::: "memory")

// SW64 swizzle: 64B rows, xor col-chunk bits [5:4] with row bits [7:8]
#define SWZ64(off) ((off) ^ (((off) >> 3) & 0x30))

// ---------------------------------------------------------------------------
// fp32 -> bf16 hi/lo split
// ---------------------------------------------------------------------------
__global__ void __launch_bounds__(256)
split_kernel(const float* __restrict__ src,
             __nv_bfloat16* __restrict__ hi,
             __nv_bfloat16* __restrict__ lo, int n4)
{
    int i = blockIdx.x * 256 + threadIdx.x;
    if (i >= n4) return;
    float4 v = reinterpret_cast<const float4*>(src)[i];
    __nv_bfloat16 h[4], l[4];
    float f[4] = {v.x, v.y, v.z, v.w};
    #pragma unroll
    for (int j = 0; j < 4; j++) {
        h[j] = __float2bfloat16(f[j]);
        l[j] = __float2bfloat16(f[j] - __bfloat162float(h[j]));
    }
    reinterpret_cast<uint2*>(hi)[i] = *reinterpret_cast<uint2*>(h);
    reinterpret_cast<uint2*>(lo)[i] = *reinterpret_cast<uint2*>(l);
}

// ---------------------------------------------------------------------------
// mma.sync GEMM: C[m,n] = sum_k A[m,k]*B[n,k] + bias[n]
// 128x128 CTA tile, BK=32, 8 warps (64x32 each), cp.async double buffer.
// D = Ahi*Bhi + Ahi*Blo + Alo*Bhi  (fp32 accumulate).
// MODE 0: row-major to C (reads given A ptrs). MODE 1/2/3: scatter to Q/K/V.
// ---------------------------------------------------------------------------
#define ARR_B    8192              // one 128x32 bf16 tile
#define STAGE_B  (4 * ARR_B)       // Ahi, Alo, Bhi, Blo  (32 KB)
#define GEMM_SMEM (2 * STAGE_B)    // 64 KB

template <int MODE>
__global__ void __launch_bounds__(256, 2)
gemm_mma_kernel(const __nv_bfloat16* __restrict__ Ahi,
                const __nv_bfloat16* __restrict__ Alo,
                const __nv_bfloat16* __restrict__ Bhi,
                const __nv_bfloat16* __restrict__ Blo,
                const float* __restrict__ bias,
                float* __restrict__ C)
{
    extern __shared__ char smem[];
    const uint32_t sbase = smem_u32(smem);
    const int tid  = threadIdx.x;
    const int lane = tid & 31;
    const int wid  = tid >> 5;
    const int bm = blockIdx.y * 128;
    const int bn = blockIdx.x * 128;
    const int wm = (wid >> 2) * 64;    // warp m offset in CTA tile
    const int wn = (wid & 3) * 32;     // warp n offset

    float acc[4][4][4];
    #pragma unroll
    for (int i = 0; i < 4; i++)
        #pragma unroll
        for (int j = 0; j < 4; j++)
            #pragma unroll
            for (int k = 0; k < 4; k++)
                acc[i][j][k] = 0.0f;

    // loader geometry: per array, 512 chunks of 16B; thread does 2
    const int r0 = tid >> 2;           // rows 0..63 (+64 on it=1)
    const int c0 = tid & 3;            // 16B chunk within 64B row

    // stage loader
    auto load_stage = [&](int s, int kc) {
        const uint32_t sb = sbase + s * STAGE_B;
        #pragma unroll
        for (int it = 0; it < 2; it++) {
            const int r = r0 + it * 64;
            const uint32_t so = SWZ64((uint32_t)(r * 64 + c0 * 16));
            const size_t ga = (size_t)(bm + r) * 1024 + kc + c0 * 8;
            const size_t gb = (size_t)(bn + r) * 1024 + kc + c0 * 8;
            CP_ASYNC16(sb + 0 * ARR_B + so, Ahi + ga);
            CP_ASYNC16(sb + 1 * ARR_B + so, Alo + ga);
            CP_ASYNC16(sb + 2 * ARR_B + so, Bhi + gb);
            CP_ASYNC16(sb + 3 * ARR_B + so, Blo + gb);
        }
    };

    load_stage(0, 0);
    CP_COMMIT();

    const int lrow = lane & 15;              // ldmatrix row within 16
    const int lcolB = (lane >> 4) << 4;      // 0 or 16 bytes (k half)

    for (int c = 0; c < 32; c++) {
        if (c + 1 < 32) {
            load_stage((c + 1) & 1, (c + 1) * 32);
            CP_COMMIT();
            CP_WAIT1();
        } else {
            CP_WAIT0();
        }
        __syncthreads();

        const uint32_t sA   = sbase + (c & 1) * STAGE_B;
        const uint32_t sAlo = sA + ARR_B;
        const uint32_t sBhi = sA + 2 * ARR_B;
        const uint32_t sBlo = sA + 3 * ARR_B;

        #pragma unroll
        for (int kk = 0; kk < 2; kk++) {
            const int colB = kk * 32 + lcolB;

            uint32_t bhi[2][4], blo[2][4];
            #pragma unroll
            for (int p = 0; p < 2; p++) {
                const uint32_t off =
                    SWZ64((uint32_t)((wn + p * 16 + lrow) * 64 + colB));
                ldsm_x4(bhi[p], sBhi + off);
                ldsm_x4(blo[p], sBlo + off);
            }

            #pragma unroll
            for (int mt = 0; mt < 4; mt++) {
                const uint32_t off =
                    SWZ64((uint32_t)((wm + mt * 16 + lrow) * 64 + colB));
                uint32_t ahi[4], alo[4];
                ldsm_x4(ahi, sA + off);
                ldsm_x4(alo, sAlo + off);

                #pragma unroll
                for (int nt = 0; nt < 4; nt++) {
                    const int p = nt >> 1, sl = nt & 1;
                    uint32_t bh[2] = { bhi[p][sl], bhi[p][sl + 2] };
                    uint32_t bl[2] = { blo[p][sl], blo[p][sl + 2] };
                    mma16816(acc[mt][nt], ahi, bh);
                    mma16816(acc[mt][nt], ahi, bl);
                    mma16816(acc[mt][nt], alo, bh);
                }
            }
        }
        __syncthreads();
    }

    // epilogue
    const int gID = lane >> 2;
    const int tig = lane & 3;
    #pragma unroll
    for (int mt = 0; mt < 4; mt++) {
        const int row0 = bm + wm + mt * 16 + gID;
        #pragma unroll
        for (int nt = 0; nt < 4; nt++) {
            const int col = bn + wn + nt * 8 + tig * 2;
            const float bb0 = bias[col];
            const float bb1 = bias[col + 1];
            #pragma unroll
            for (int half = 0; half < 2; half++) {
                const int m = row0 + half * 8;
                float2 v = make_float2(acc[mt][nt][half * 2 + 0] + bb0,
                                       acc[mt][nt][half * 2 + 1] + bb1);
                if (MODE == 0) {
                    *reinterpret_cast<float2*>(&C[(size_t)m * 1024 + col]) = v;
                } else {
                    const int b = m >> 11, s = m & 2047;
                    const int h = col >> 6, d = col & 63;
                    const size_t idx =
                        ((size_t)((b << 4) + h) * SEQ + s) * HEAD_DIM + d;
                    if (MODE == 1)
                        *reinterpret_cast<float2*>(&g_Q[idx]) = v;
                    else if (MODE == 2)
                        *reinterpret_cast<float2*>(&g_K[idx]) = v;
                    else
                        *reinterpret_cast<float2*>(&g_V[idx]) = v;
                }
            }
        }
    }
}

// ---------------------------------------------------------------------------
// Flash attention, fp32 (unchanged — at FFMA roofline; mma.sync port is next)
// ---------------------------------------------------------------------------
#define QS(k, q) smQ[(k) * 68 + (q)]
#define KS(k, j) smK[(k) * 68 + (j)]
#define SS(q, j) smS[(q) * 68 + (j)]
#define VS(j, d) smV[(j) * 64 + (d)]
#define ATTN_SMEM_FLOATS (3 * 64 * 68 + 64 * 64)

__global__ void __launch_bounds__(256)
attn_kernel(const int* __restrict__ mask)
{
    extern __shared__ float sm[];
    float* smQ = sm;
    float* smK = smQ + 64 * 68;
    float* smS = smK + 64 * 68;
    float* smV = smS + 64 * 68;

    __shared__ float m_s[64];
    __shared__ float l_s[64];
    __shared__ float alpha_s[64];
    __shared__ int   msk_s[64];

    int qb = blockIdx.x;
    int h  = blockIdx.y;
    int b  = blockIdx.z;
    int tid = threadIdx.x;

    const float* Qh = g_Q + ((size_t)(b * N_HEADS + h) * SEQ + qb * 64) * HEAD_DIM;
    const float* Kh = g_K + ((size_t)(b * N_HEADS + h) * SEQ) * HEAD_DIM;
    const float* Vh = g_V + ((size_t)(b * N_HEADS + h) * SEQ) * HEAD_DIM;
    const int* maskb = mask + (size_t)b * SEQ;

    for (int i = tid; i < 64 * 64; i += 256) {
        int q = i >> 6, d = i & 63;
        QS(d, q) = Qh[q * 64 + d] * 0.125f;
    }
    if (tid < 64) { m_s[tid] = -INFINITY; l_s[tid] = 0.0f; }

    int tx = tid & 15;
    int ty = tid >> 4;
    float o[4][4];
    #pragma unroll
    for (int i = 0; i < 4; i++)
        #pragma unroll
        for (int j = 0; j < 4; j++)
            o[i][j] = 0.0f;

    for (int t = 0; t < SEQ / 64; t++) {
        __syncthreads();

        for (int i = tid; i < 64 * 64; i += 256) {
            int j = i >> 6, d = i & 63;
            float kv = Kh[(size_t)(t * 64 + j) * 64 + d];
            float vv = Vh[(size_t)(t * 64 + j) * 64 + d];
            KS(d, j) = kv;
            VS(j, d) = vv;
        }
        if (tid < 64) msk_s[tid] = maskb[t * 64 + tid];
        __syncthreads();

        float sacc[4][4];
        #pragma unroll
        for (int i = 0; i < 4; i++)
            #pragma unroll
            for (int j = 0; j < 4; j++)
                sacc[i][j] = 0.0f;

        #pragma unroll 8
        for (int k = 0; k < 64; k++) {
            float4 qv = *reinterpret_cast<const float4*>(&QS(k, ty * 4));
            float4 kv = *reinterpret_cast<const float4*>(&KS(k, tx * 4));
            float qa[4] = {qv.x, qv.y, qv.z, qv.w};
            float ka[4] = {kv.x, kv.y, kv.z, kv.w};
            #pragma unroll
            for (int i = 0; i < 4; i++)
                #pragma unroll
                for (int j = 0; j < 4; j++)
                    sacc[i][j] += qa[i] * ka[j];
        }

        #pragma unroll
        for (int i = 0; i < 4; i++)
            #pragma unroll
            for (int j = 0; j < 4; j++) {
                int jj = tx * 4 + j;
                SS(ty * 4 + i, jj) = (msk_s[jj] != 0) ? sacc[i][j] : -1.0e10f;
            }
        __syncthreads();

        {
            int rr = tid >> 2;
            int seg = tid & 3;
            float* Srow = &SS(rr, 0);
            float lm = -INFINITY;
            #pragma unroll
            for (int c = 0; c < 16; c++)
                lm = fmaxf(lm, Srow[seg * 16 + c]);
            lm = fmaxf(lm, __shfl_xor_sync(0xffffffffu, lm, 1));
            lm = fmaxf(lm, __shfl_xor_sync(0xffffffffu, lm, 2));

            float m_old = m_s[rr];
            float m_new = fmaxf(m_old, lm);

            float lsum = 0.0f;
            #pragma unroll
            for (int c = 0; c < 16; c++) {
                float p = __expf(Srow[seg * 16 + c] - m_new);
                Srow[seg * 16 + c] = p;
                lsum += p;
            }
            lsum += __shfl_xor_sync(0xffffffffu, lsum, 1);
            lsum += __shfl_xor_sync(0xffffffffu, lsum, 2);

            if (seg == 0) {
                float a = __expf(m_old - m_new);
                alpha_s[rr] = a;
                l_s[rr] = l_s[rr] * a + lsum;
                m_s[rr] = m_new;
            }
        }
        __syncthreads();

        float al[4];
        #pragma unroll
        for (int i = 0; i < 4; i++) al[i] = alpha_s[ty * 4 + i];
        #pragma unroll
        for (int i = 0; i < 4; i++)
            #pragma unroll
            for (int j = 0; j < 4; j++)
                o[i][j] *= al[i];

        #pragma unroll 8
        for (int j = 0; j < 64; j++) {
            float4 vv = *reinterpret_cast<const float4*>(&VS(j, tx * 4));
            float va[4] = {vv.x, vv.y, vv.z, vv.w};
            float p0 = SS(ty * 4 + 0, j);
            float p1 = SS(ty * 4 + 1, j);
            float p2 = SS(ty * 4 + 2, j);
            float p3 = SS(ty * 4 + 3, j);
            #pragma unroll
            for (int jj = 0; jj < 4; jj++) {
                o[0][jj] += p0 * va[jj];
                o[1][jj] += p1 * va[jj];
                o[2][jj] += p2 * va[jj];
                o[3][jj] += p3 * va[jj];
            }
        }
    }

    #pragma unroll
    for (int i = 0; i < 4; i++) {
        int q = qb * 64 + ty * 4 + i;
        float invl = 1.0f / l_s[ty * 4 + i];
        #pragma unroll
        for (int j = 0; j < 4; j++) {
            int d = tx * 4 + j;
            g_AO[((size_t)b * SEQ + q) * D_MODEL + h * HEAD_DIM + d] = o[i][j] * invl;
        }
    }
}

// ---------------------------------------------------------------------------
// Launcher
// ---------------------------------------------------------------------------
extern "C" void kernel_launch(void* const* d_in, const int* in_sizes, int n_in,
                              void* d_out, int out_size)
{
    const float* x    = (const float*)d_in[0];
    const int*   mask = (const int*)  d_in[1];
    const float* Wq   = (const float*)d_in[2];
    const float* bq   = (const float*)d_in[3];
    const float* Wk   = (const float*)d_in[4];
    const float* bk   = (const float*)d_in[5];
    const float* Wv   = (const float*)d_in[6];
    const float* bv   = (const float*)d_in[7];
    const float* Wo   = (const float*)d_in[8];
    const float* bo   = (const float*)d_in[9];
    float* out = (float*)d_out;

    __nv_bfloat16 *xhi, *xlo, *aohi, *aolo;
    __nv_bfloat16 *wqhi, *wqlo, *wkhi, *wklo, *wvhi, *wvlo, *wohi, *wolo;
    cudaGetSymbolAddress((void**)&xhi,  g_xhi);
    cudaGetSymbolAddress((void**)&xlo,  g_xlo);
    cudaGetSymbolAddress((void**)&aohi, g_aohi);
    cudaGetSymbolAddress((void**)&aolo, g_aolo);
    cudaGetSymbolAddress((void**)&wqhi, g_wqhi);
    cudaGetSymbolAddress((void**)&wqlo, g_wqlo);
    cudaGetSymbolAddress((void**)&wkhi, g_wkhi);
    cudaGetSymbolAddress((void**)&wklo, g_wklo);
    cudaGetSymbolAddress((void**)&wvhi, g_wvhi);
    cudaGetSymbolAddress((void**)&wvlo, g_wvlo);
    cudaGetSymbolAddress((void**)&wohi, g_wohi);
    cudaGetSymbolAddress((void**)&wolo, g_wolo);

    cudaFuncSetAttribute(gemm_mma_kernel<0>, cudaFuncAttributeMaxDynamicSharedMemorySize, GEMM_SMEM);
    cudaFuncSetAttribute(gemm_mma_kernel<1>, cudaFuncAttributeMaxDynamicSharedMemorySize, GEMM_SMEM);
    cudaFuncSetAttribute(gemm_mma_kernel<2>, cudaFuncAttributeMaxDynamicSharedMemorySize, GEMM_SMEM);
    cudaFuncSetAttribute(gemm_mma_kernel<3>, cudaFuncAttributeMaxDynamicSharedMemorySize, GEMM_SMEM);

    const int nx4 = M_TOT * D_MODEL / 4;      // 1048576
    const int nw4 = D_MODEL * D_MODEL / 4;    // 262144

    split_kernel<<<nx4 / 256, 256>>>(x,  xhi, xlo, nx4);
    split_kernel<<<nw4 / 256, 256>>>(Wq, wqhi, wqlo, nw4);
    split_kernel<<<nw4 / 256, 256>>>(Wk, wkhi, wklo, nw4);
    split_kernel<<<nw4 / 256, 256>>>(Wv, wvhi, wvlo, nw4);
    split_kernel<<<nw4 / 256, 256>>>(Wo, wohi, wolo, nw4);

    dim3 ggrid(D_MODEL / 128, M_TOT / 128);   // (8, 32)

    gemm_mma_kernel<1><<<ggrid, 256, GEMM_SMEM>>>(xhi, xlo, wqhi, wqlo, bq, nullptr);
    gemm_mma_kernel<2><<<ggrid, 256, GEMM_SMEM>>>(xhi, xlo, wkhi, wklo, bk, nullptr);
    gemm_mma_kernel<3><<<ggrid, 256, GEMM_SMEM>>>(xhi, xlo, wvhi, wvlo, bv, nullptr);

    const int attn_smem = ATTN_SMEM_FLOATS * (int)sizeof(float);
    cudaFuncSetAttribute(attn_kernel, cudaFuncAttributeMaxDynamicSharedMemorySize, attn_smem);
    attn_kernel<<<dim3(SEQ / 64, N_HEADS, BATCH), 256, attn_smem>>>(mask);

    float* ao;
    cudaGetSymbolAddress((void**)&ao, g_AO);
    split_kernel<<<nx4 / 256, 256>>>(ao, aohi, aolo, nx4);
    gemm_mma_kernel<0><<<ggrid, 256, GEMM_SMEM>>>(aohi, aolo, wohi, wolo, bo, out);
}

// round 4
// speedup vs baseline: 2.8577x; 2.0016x over previous
#include <cuda_runtime.h>
#include <cuda_bf16.h>
#include <math.h>
#include <stdint.h>

// Problem constants
#define D_MODEL   1024
#define N_HEADS   16
#define HEAD_DIM  64
#define SEQ       2048
#define BATCH     2
#define M_TOT     (BATCH * SEQ)      // 4096

// ---------------------------------------------------------------------------
// Scratch (device globals — no allocations allowed)
// ---------------------------------------------------------------------------
// bf16 hi/lo splits of inputs/weights
__device__ __align__(128) __nv_bfloat16 g_xhi [M_TOT * D_MODEL];
__device__ __align__(128) __nv_bfloat16 g_xlo [M_TOT * D_MODEL];
__device__ __align__(128) __nv_bfloat16 g_wqhi[D_MODEL * D_MODEL];
__device__ __align__(128) __nv_bfloat16 g_wqlo[D_MODEL * D_MODEL];
__device__ __align__(128) __nv_bfloat16 g_wkhi[D_MODEL * D_MODEL];
__device__ __align__(128) __nv_bfloat16 g_wklo[D_MODEL * D_MODEL];
__device__ __align__(128) __nv_bfloat16 g_wvhi[D_MODEL * D_MODEL];
__device__ __align__(128) __nv_bfloat16 g_wvlo[D_MODEL * D_MODEL];
__device__ __align__(128) __nv_bfloat16 g_wohi[D_MODEL * D_MODEL];
__device__ __align__(128) __nv_bfloat16 g_wolo[D_MODEL * D_MODEL];

// Q/K/V in [b][h][s][d], bf16 hi/lo (written directly by projection epilogues)
#define QKV_ELEMS (BATCH * N_HEADS * SEQ * HEAD_DIM)
__device__ __align__(128) __nv_bfloat16 g_qhi[QKV_ELEMS];
__device__ __align__(128) __nv_bfloat16 g_qlo[QKV_ELEMS];
__device__ __align__(128) __nv_bfloat16 g_khi[QKV_ELEMS];
__device__ __align__(128) __nv_bfloat16 g_klo[QKV_ELEMS];
__device__ __align__(128) __nv_bfloat16 g_vhi[QKV_ELEMS];
__device__ __align__(128) __nv_bfloat16 g_vlo[QKV_ELEMS];

// attention output [b][s][h*64+d], bf16 hi/lo (written directly by attention)
__device__ __align__(128) __nv_bfloat16 g_aohi[M_TOT * D_MODEL];
__device__ __align__(128) __nv_bfloat16 g_aolo[M_TOT * D_MODEL];

// ---------------------------------------------------------------------------
// Base-ISA helpers
// ---------------------------------------------------------------------------
__device__ __forceinline__ uint32_t smem_u32(const void* p) {
    uint32_t a;
    asm("{ .reg .u64 t; cvta.to.shared.u64 t, %1; cvt.u32.u64 %0, t; }"
        : "=r"(a) : "l"(p));
    return a;
}

__device__ __forceinline__ void ldsm_x4(uint32_t* r, uint32_t addr) {
    asm volatile("ldmatrix.sync.aligned.m8n8.x4.shared.b16 {%0,%1,%2,%3}, [%4];"
                 : "=r"(r[0]), "=r"(r[1]), "=r"(r[2]), "=r"(r[3]) : "r"(addr));
}
__device__ __forceinline__ void ldsm_x4_t(uint32_t* r, uint32_t addr) {
    asm volatile("ldmatrix.sync.aligned.m8n8.x4.trans.shared.b16 {%0,%1,%2,%3}, [%4];"
                 : "=r"(r[0]), "=r"(r[1]), "=r"(r[2]), "=r"(r[3]) : "r"(addr));
}

__device__ __forceinline__ void mma16816(float* c, const uint32_t* a,
                                         const uint32_t* b) {
    asm volatile(
        "mma.sync.aligned.m16n8k16.row.col.f32.bf16.bf16.f32 "
        "{%0,%1,%2,%3}, {%4,%5,%6,%7}, {%8,%9}, {%0,%1,%2,%3};"
        : "+f"(c[0]), "+f"(c[1]), "+f"(c[2]), "+f"(c[3])
        : "r"(a[0]), "r"(a[1]), "r"(a[2]), "r"(a[3]), "r"(b[0]), "r"(b[1]));
}

#define CP_ASYNC16(dst, src) \
    asm volatile("cp.async.cg.shared.global [%0], [%1], 16;" \
        :: "r"(dst), "l"(src))
#define CP_ASYNC4(dst, src) \
    asm volatile("cp.async.ca.shared.global [%0], [%1], 4;" \
        :: "r"(dst), "l"(src))
#define CP_COMMIT() asm volatile("cp.async.commit_group;" ::: "memory")
#define CP_WAIT1()  asm volatile("cp.async.wait_group 1;" ::: "memory")
#define CP_WAIT0()  asm volatile("cp.async.wait_group 0;" ::: "memory")

#define SWZ64(off)  ((off) ^ (((off) >> 3) & 0x30))
#define SWZ128(off) ((off) ^ (((off) >> 3) & 0x70))

__device__ __forceinline__ uint32_t packbf(__nv_bfloat16 lo, __nv_bfloat16 hi) {
    __nv_bfloat162 t = __halves2bfloat162(lo, hi);   // .x = lo half (bits 0-15)
    return *reinterpret_cast<uint32_t*>(&t);
}
__device__ __forceinline__ uint32_t split_pack_hi(float a, float b,
                                                  uint32_t& lop) {
    __nv_bfloat16 ha = __float2bfloat16(a);
    __nv_bfloat16 hb = __float2bfloat16(b);
    __nv_bfloat16 la = __float2bfloat16(a - __bfloat162float(ha));
    __nv_bfloat16 lb = __float2bfloat16(b - __bfloat162float(hb));
    lop = packbf(la, lb);
    return packbf(ha, hb);
}

// ---------------------------------------------------------------------------
// fp32 -> bf16 hi/lo split
// ---------------------------------------------------------------------------
__global__ void __launch_bounds__(256)
split_kernel(const float* __restrict__ src,
             __nv_bfloat16* __restrict__ hi,
             __nv_bfloat16* __restrict__ lo, int n4)
{
    int i = blockIdx.x * 256 + threadIdx.x;
    if (i >= n4) return;
    float4 v = reinterpret_cast<const float4*>(src)[i];
    __nv_bfloat16 h[4], l[4];
    float f[4] = {v.x, v.y, v.z, v.w};
    #pragma unroll
    for (int j = 0; j < 4; j++) {
        h[j] = __float2bfloat16(f[j]);
        l[j] = __float2bfloat16(f[j] - __bfloat162float(h[j]));
    }
    reinterpret_cast<uint2*>(hi)[i] = *reinterpret_cast<uint2*>(h);
    reinterpret_cast<uint2*>(lo)[i] = *reinterpret_cast<uint2*>(l);
}

// ---------------------------------------------------------------------------
// mma.sync GEMM (unchanged core from R3): C[m,n] = sum_k A[m,k]*B[n,k]+bias[n]
// MODE 0: fp32 row-major to C.
// MODE 1: Q — scale by 0.125, split bf16 hi/lo, scatter [b][h][s][d].
// MODE 2/3: K/V — split bf16 hi/lo, scatter [b][h][s][d].
// ---------------------------------------------------------------------------
#define ARR_B    8192
#define STAGE_B  (4 * ARR_B)
#define GEMM_SMEM (2 * STAGE_B)

template <int MODE>
__global__ void __launch_bounds__(256, 2)
gemm_mma_kernel(const __nv_bfloat16* __restrict__ Ahi,
                const __nv_bfloat16* __restrict__ Alo,
                const __nv_bfloat16* __restrict__ Bhi,
                const __nv_bfloat16* __restrict__ Blo,
                const float* __restrict__ bias,
                float* __restrict__ C)
{
    extern __shared__ char smem[];
    const uint32_t sbase = smem_u32(smem);
    const int tid  = threadIdx.x;
    const int lane = tid & 31;
    const int wid  = tid >> 5;
    const int bm = blockIdx.y * 128;
    const int bn = blockIdx.x * 128;
    const int wm = (wid >> 2) * 64;
    const int wn = (wid & 3) * 32;

    float acc[4][4][4];
    #pragma unroll
    for (int i = 0; i < 4; i++)
        #pragma unroll
        for (int j = 0; j < 4; j++)
            #pragma unroll
            for (int k = 0; k < 4; k++)
                acc[i][j][k] = 0.0f;

    const int r0 = tid >> 2;
    const int c0 = tid & 3;

    auto load_stage = [&](int s, int kc) {
        const uint32_t sb = sbase + s * STAGE_B;
        #pragma unroll
        for (int it = 0; it < 2; it++) {
            const int r = r0 + it * 64;
            const uint32_t so = SWZ64((uint32_t)(r * 64 + c0 * 16));
            const size_t ga = (size_t)(bm + r) * 1024 + kc + c0 * 8;
            const size_t gb = (size_t)(bn + r) * 1024 + kc + c0 * 8;
            CP_ASYNC16(sb + 0 * ARR_B + so, Ahi + ga);
            CP_ASYNC16(sb + 1 * ARR_B + so, Alo + ga);
            CP_ASYNC16(sb + 2 * ARR_B + so, Bhi + gb);
            CP_ASYNC16(sb + 3 * ARR_B + so, Blo + gb);
        }
    };

    load_stage(0, 0);
    CP_COMMIT();

    const int lrow = lane & 15;
    const int lcolB = (lane >> 4) << 4;

    for (int c = 0; c < 32; c++) {
        if (c + 1 < 32) {
            load_stage((c + 1) & 1, (c + 1) * 32);
            CP_COMMIT();
            CP_WAIT1();
        } else {
            CP_WAIT0();
        }
        __syncthreads();

        const uint32_t sA   = sbase + (c & 1) * STAGE_B;
        const uint32_t sAlo = sA + ARR_B;
        const uint32_t sBhi = sA + 2 * ARR_B;
        const uint32_t sBlo = sA + 3 * ARR_B;

        #pragma unroll
        for (int kk = 0; kk < 2; kk++) {
            const int colB = kk * 32 + lcolB;

            uint32_t bhi[2][4], blo[2][4];
            #pragma unroll
            for (int p = 0; p < 2; p++) {
                const uint32_t off =
                    SWZ64((uint32_t)((wn + p * 16 + lrow) * 64 + colB));
                ldsm_x4(bhi[p], sBhi + off);
                ldsm_x4(blo[p], sBlo + off);
            }

            #pragma unroll
            for (int mt = 0; mt < 4; mt++) {
                const uint32_t off =
                    SWZ64((uint32_t)((wm + mt * 16 + lrow) * 64 + colB));
                uint32_t ahi[4], alo[4];
                ldsm_x4(ahi, sA + off);
                ldsm_x4(alo, sAlo + off);

                #pragma unroll
                for (int nt = 0; nt < 4; nt++) {
                    const int p = nt >> 1, sl = nt & 1;
                    uint32_t bh[2] = { bhi[p][sl], bhi[p][sl + 2] };
                    uint32_t bl[2] = { blo[p][sl], blo[p][sl + 2] };
                    mma16816(acc[mt][nt], ahi, bh);
                    mma16816(acc[mt][nt], ahi, bl);
                    mma16816(acc[mt][nt], alo, bh);
                }
            }
        }
        __syncthreads();
    }

    const int gID = lane >> 2;
    const int tig = lane & 3;
    #pragma unroll
    for (int mt = 0; mt < 4; mt++) {
        const int row0 = bm + wm + mt * 16 + gID;
        #pragma unroll
        for (int nt = 0; nt < 4; nt++) {
            const int col = bn + wn + nt * 8 + tig * 2;
            const float bb0 = bias[col];
            const float bb1 = bias[col + 1];
            #pragma unroll
            for (int half = 0; half < 2; half++) {
                const int m = row0 + half * 8;
                float vx = acc[mt][nt][half * 2 + 0] + bb0;
                float vy = acc[mt][nt][half * 2 + 1] + bb1;
                if (MODE == 0) {
                    *reinterpret_cast<float2*>(&C[(size_t)m * 1024 + col]) =
                        make_float2(vx, vy);
                } else {
                    if (MODE == 1) { vx *= 0.125f; vy *= 0.125f; }
                    uint32_t lop;
                    const uint32_t hip = split_pack_hi(vx, vy, lop);
                    const int b = m >> 11, s = m & 2047;
                    const int hh = col >> 6, d = col & 63;
                    const size_t idx =
                        ((size_t)((b << 4) + hh) * SEQ + s) * HEAD_DIM + d;
                    if (MODE == 1) {
                        *reinterpret_cast<uint32_t*>(&g_qhi[idx]) = hip;
                        *reinterpret_cast<uint32_t*>(&g_qlo[idx]) = lop;
                    } else if (MODE == 2) {
                        *reinterpret_cast<uint32_t*>(&g_khi[idx]) = hip;
                        *reinterpret_cast<uint32_t*>(&g_klo[idx]) = lop;
                    } else {
                        *reinterpret_cast<uint32_t*>(&g_vhi[idx]) = hip;
                        *reinterpret_cast<uint32_t*>(&g_vlo[idx]) = lop;
                    }
                }
            }
        }
    }
}

// ---------------------------------------------------------------------------
// Flash attention on mma.sync bf16 hi/lo.
// CTA: 256 threads (8 warps), BQ=128 (warp w owns q rows w*16..w*16+15),
// BK=64, cp.async double-buffered K/V(+mask), online softmax in registers.
// smem layout (bytes):
//   [0)      Qhi  128x64 bf16  (16384)
//   [16384)  Qlo               (16384)
//   [32768 + s*32768): stage s: Khi(8192) Klo(8192) Vhi(8192) Vlo(8192)
//   [98304 + s*256):  mask ints (64 per stage)
// all tile rows are 128B; SWZ128 swizzle.
// ---------------------------------------------------------------------------
#define ATTN_SMEM 98816

__global__ void __launch_bounds__(256, 1)
attn_mma_kernel(const int* __restrict__ mask)
{
    extern __shared__ char smn[];
    const uint32_t sb = smem_u32(smn);
    const int tid  = threadIdx.x;
    const int lane = tid & 31;
    const int w    = tid >> 5;
    const int qb   = blockIdx.x;
    const int h    = blockIdx.y;
    const int b    = blockIdx.z;
    const int bh   = b * N_HEADS + h;
    const int g    = lane >> 2;
    const int tig  = lane & 3;
    const int lrow = lane & 15;
    const int lhi16 = (lane >> 4) & 1;

    const __nv_bfloat16* Qhi = g_qhi + ((size_t)bh * SEQ + qb * 128) * 64;
    const __nv_bfloat16* Qlo = g_qlo + ((size_t)bh * SEQ + qb * 128) * 64;
    const __nv_bfloat16* Khi = g_khi + (size_t)bh * SEQ * 64;
    const __nv_bfloat16* Klo = g_klo + (size_t)bh * SEQ * 64;
    const __nv_bfloat16* Vhi = g_vhi + (size_t)bh * SEQ * 64;
    const __nv_bfloat16* Vlo = g_vlo + (size_t)bh * SEQ * 64;
    const int* maskb = mask + (size_t)b * SEQ;

    // ---- Q tile load (hi+lo): 2048 x 16B chunks ----
    #pragma unroll
    for (int i = 0; i < 8; i++) {
        const int idx = i * 256 + tid;
        const int arr = idx >> 10;             // 0 hi, 1 lo
        const int rem = idx & 1023;
        const int r = rem >> 3, cc = rem & 7;
        const uint32_t dst =
            sb + arr * 16384 + SWZ128((uint32_t)(r * 128 + cc * 16));
        const __nv_bfloat16* src = (arr ? Qlo : Qhi) + r * 64 + cc * 8;
        CP_ASYNC16(dst, src);
    }

    auto load_kv = [&](int s, int t) {
        const uint32_t stb = sb + 32768 + s * 32768;
        #pragma unroll
        for (int i = 0; i < 8; i++) {
            const int idx = i * 256 + tid;
            const int arr = idx >> 9;          // 0 khi,1 klo,2 vhi,3 vlo
            const int rem = idx & 511;
            const int r = rem >> 3, cc = rem & 7;
            const uint32_t dst =
                stb + arr * 8192 + SWZ128((uint32_t)(r * 128 + cc * 16));
            const __nv_bfloat16* base =
                (arr == 0) ? Khi : (arr == 1) ? Klo : (arr == 2) ? Vhi : Vlo;
            CP_ASYNC16(dst, base + (size_t)(t * 64 + r) * 64 + cc * 8);
        }
        if (tid < 64) {
            const uint32_t mdst = sb + 98304 + s * 256 + tid * 4;
            CP_ASYNC4(mdst, maskb + t * 64 + tid);
        }
    };

    load_kv(0, 0);
    CP_COMMIT();

    float o[8][4];
    #pragma unroll
    for (int nt = 0; nt < 8; nt++)
        #pragma unroll
        for (int e = 0; e < 4; e++)
            o[nt][e] = 0.0f;
    float m0 = -INFINITY, m1 = -INFINITY, l0 = 0.0f, l1 = 0.0f;

    for (int t = 0; t < 32; t++) {
        if (t + 1 < 32) {
            load_kv((t + 1) & 1, t + 1);
            CP_COMMIT();
            CP_WAIT1();
        } else {
            CP_WAIT0();
        }
        __syncthreads();

        const int s = t & 1;
        const uint32_t sK   = sb + 32768 + s * 32768;
        const uint32_t sKlo = sK + 8192;
        const uint32_t sV   = sK + 16384;
        const uint32_t sVlo = sK + 24576;

        // ---- S = Q K^T (3-term bf16) ----
        float sacc[8][4];
        #pragma unroll
        for (int nt = 0; nt < 8; nt++)
            #pragma unroll
            for (int e = 0; e < 4; e++)
                sacc[nt][e] = 0.0f;

        #pragma unroll
        for (int ks = 0; ks < 4; ks++) {
            const uint32_t offq = SWZ128(
                (uint32_t)((w * 16 + lrow) * 128 + (ks * 16 + lhi16 * 8) * 2));
            uint32_t ah[4], al[4];
            ldsm_x4(ah, sb + offq);
            ldsm_x4(al, sb + 16384 + offq);
            #pragma unroll
            for (int np = 0; np < 4; np++) {
                const uint32_t offk = SWZ128(
                    (uint32_t)((np * 16 + lrow) * 128 + (ks * 16 + lhi16 * 8) * 2));
                uint32_t kh[4], kl[4];
                ldsm_x4(kh, sK + offk);
                ldsm_x4(kl, sKlo + offk);
                uint32_t b0h[2] = {kh[0], kh[2]}, b0l[2] = {kl[0], kl[2]};
                uint32_t b1h[2] = {kh[1], kh[3]}, b1l[2] = {kl[1], kl[3]};
                mma16816(sacc[np * 2],     ah, b0h);
                mma16816(sacc[np * 2],     ah, b0l);
                mma16816(sacc[np * 2],     al, b0h);
                mma16816(sacc[np * 2 + 1], ah, b1h);
                mma16816(sacc[np * 2 + 1], ah, b1l);
                mma16816(sacc[np * 2 + 1], al, b1h);
            }
        }

        // ---- mask ----
        const int* mskp = (const int*)(smn + 98304 + s * 256);
        const int jb = tig * 2;
        #pragma unroll
        for (int nt = 0; nt < 8; nt++) {
            if (mskp[nt * 8 + jb] == 0) {
                sacc[nt][0] = -1.0e10f; sacc[nt][2] = -1.0e10f;
            }
            if (mskp[nt * 8 + jb + 1] == 0) {
                sacc[nt][1] = -1.0e10f; sacc[nt][3] = -1.0e10f;
            }
        }

        // ---- online softmax (rows g and g+8; quad shares rows) ----
        float r0 = -INFINITY, r1 = -INFINITY;
        #pragma unroll
        for (int nt = 0; nt < 8; nt++) {
            r0 = fmaxf(r0, fmaxf(sacc[nt][0], sacc[nt][1]));
            r1 = fmaxf(r1, fmaxf(sacc[nt][2], sacc[nt][3]));
        }
        r0 = fmaxf(r0, __shfl_xor_sync(0xffffffffu, r0, 1));
        r0 = fmaxf(r0, __shfl_xor_sync(0xffffffffu, r0, 2));
        r1 = fmaxf(r1, __shfl_xor_sync(0xffffffffu, r1, 1));
        r1 = fmaxf(r1, __shfl_xor_sync(0xffffffffu, r1, 2));

        const float mn0 = fmaxf(m0, r0), mn1 = fmaxf(m1, r1);
        const float a0 = __expf(m0 - mn0), a1 = __expf(m1 - mn1);
        m0 = mn0; m1 = mn1;

        float ls0 = 0.0f, ls1 = 0.0f;
        #pragma unroll
        for (int nt = 0; nt < 8; nt++) {
            sacc[nt][0] = __expf(sacc[nt][0] - mn0);
            sacc[nt][1] = __expf(sacc[nt][1] - mn0);
            sacc[nt][2] = __expf(sacc[nt][2] - mn1);
            sacc[nt][3] = __expf(sacc[nt][3] - mn1);
            ls0 += sacc[nt][0] + sacc[nt][1];
            ls1 += sacc[nt][2] + sacc[nt][3];
            o[nt][0] *= a0; o[nt][1] *= a0;
            o[nt][2] *= a1; o[nt][3] *= a1;
        }
        l0 = l0 * a0 + ls0;
        l1 = l1 * a1 + ls1;

        // ---- P fragments (C-layout == A-layout identity) ----
        uint32_t pfh[4][4], pfl[4][4];
        #pragma unroll
        for (int ks = 0; ks < 4; ks++) {
            #pragma unroll
            for (int half = 0; half < 2; half++) {
                const int nt = 2 * ks + half;
                pfh[ks][half * 2 + 0] =
                    split_pack_hi(sacc[nt][0], sacc[nt][1], pfl[ks][half * 2 + 0]);
                pfh[ks][half * 2 + 1] =
                    split_pack_hi(sacc[nt][2], sacc[nt][3], pfl[ks][half * 2 + 1]);
            }
        }

        // ---- O += P V (3-term; V^T via ldmatrix.trans) ----
        #pragma unroll
        for (int ks = 0; ks < 4; ks++) {
            #pragma unroll
            for (int np = 0; np < 4; np++) {
                const uint32_t offv = SWZ128(
                    (uint32_t)((ks * 16 + lrow) * 128 + (np * 16 + lhi16 * 8) * 2));
                uint32_t vh[4], vl[4];
                ldsm_x4_t(vh, sV + offv);
                ldsm_x4_t(vl, sVlo + offv);
                uint32_t b0h[2] = {vh[0], vh[1]}, b0l[2] = {vl[0], vl[1]};
                uint32_t b1h[2] = {vh[2], vh[3]}, b1l[2] = {vl[2], vl[3]};
                mma16816(o[np * 2],     pfh[ks], b0h);
                mma16816(o[np * 2],     pfh[ks], b0l);
                mma16816(o[np * 2],     pfl[ks], b0h);
                mma16816(o[np * 2 + 1], pfh[ks], b1h);
                mma16816(o[np * 2 + 1], pfh[ks], b1l);
                mma16816(o[np * 2 + 1], pfl[ks], b1h);
            }
        }
        __syncthreads();
    }

    // ---- finalize ----
    l0 += __shfl_xor_sync(0xffffffffu, l0, 1);
    l0 += __shfl_xor_sync(0xffffffffu, l0, 2);
    l1 += __shfl_xor_sync(0xffffffffu, l1, 1);
    l1 += __shfl_xor_sync(0xffffffffu, l1, 2);
    const float inv0 = 1.0f / l0;
    const float inv1 = 1.0f / l1;

    const int row0 = qb * 128 + w * 16 + g;
    #pragma unroll
    for (int nt = 0; nt < 8; nt++) {
        const int col = h * 64 + nt * 8 + tig * 2;
        uint32_t lop;
        uint32_t hip = split_pack_hi(o[nt][0] * inv0, o[nt][1] * inv0, lop);
        size_t idx = ((size_t)b * SEQ + row0) * D_MODEL + col;
        *reinterpret_cast<uint32_t*>(&g_aohi[idx]) = hip;
        *reinterpret_cast<uint32_t*>(&g_aolo[idx]) = lop;

        hip = split_pack_hi(o[nt][2] * inv1, o[nt][3] * inv1, lop);
        idx = ((size_t)b * SEQ + row0 + 8) * D_MODEL + col;
        *reinterpret_cast<uint32_t*>(&g_aohi[idx]) = hip;
        *reinterpret_cast<uint32_t*>(&g_aolo[idx]) = lop;
    }
}

// ---------------------------------------------------------------------------
// Launcher
// ---------------------------------------------------------------------------
extern "C" void kernel_launch(void* const* d_in, const int* in_sizes, int n_in,
                              void* d_out, int out_size)
{
    const float* x    = (const float*)d_in[0];
    const int*   mask = (const int*)  d_in[1];
    const float* Wq   = (const float*)d_in[2];
    const float* bq   = (const float*)d_in[3];
    const float* Wk   = (const float*)d_in[4];
    const float* bk   = (const float*)d_in[5];
    const float* Wv   = (const float*)d_in[6];
    const float* bv   = (const float*)d_in[7];
    const float* Wo   = (const float*)d_in[8];
    const float* bo   = (const float*)d_in[9];
    float* out = (float*)d_out;

    __nv_bfloat16 *xhi, *xlo, *aohi, *aolo;
    __nv_bfloat16 *wqhi, *wqlo, *wkhi, *wklo, *wvhi, *wvlo, *wohi, *wolo;
    cudaGetSymbolAddress((void**)&xhi,  g_xhi);
    cudaGetSymbolAddress((void**)&xlo,  g_xlo);
    cudaGetSymbolAddress((void**)&aohi, g_aohi);
    cudaGetSymbolAddress((void**)&aolo, g_aolo);
    cudaGetSymbolAddress((void**)&wqhi, g_wqhi);
    cudaGetSymbolAddress((void**)&wqlo, g_wqlo);
    cudaGetSymbolAddress((void**)&wkhi, g_wkhi);
    cudaGetSymbolAddress((void**)&wklo, g_wklo);
    cudaGetSymbolAddress((void**)&wvhi, g_wvhi);
    cudaGetSymbolAddress((void**)&wvlo, g_wvlo);
    cudaGetSymbolAddress((void**)&wohi, g_wohi);
    cudaGetSymbolAddress((void**)&wolo, g_wolo);

    cudaFuncSetAttribute(gemm_mma_kernel<0>, cudaFuncAttributeMaxDynamicSharedMemorySize, GEMM_SMEM);
    cudaFuncSetAttribute(gemm_mma_kernel<1>, cudaFuncAttributeMaxDynamicSharedMemorySize, GEMM_SMEM);
    cudaFuncSetAttribute(gemm_mma_kernel<2>, cudaFuncAttributeMaxDynamicSharedMemorySize, GEMM_SMEM);
    cudaFuncSetAttribute(gemm_mma_kernel<3>, cudaFuncAttributeMaxDynamicSharedMemorySize, GEMM_SMEM);
    cudaFuncSetAttribute(attn_mma_kernel,    cudaFuncAttributeMaxDynamicSharedMemorySize, ATTN_SMEM);

    const int nx4 = M_TOT * D_MODEL / 4;
    const int nw4 = D_MODEL * D_MODEL / 4;

    split_kernel<<<nx4 / 256, 256>>>(x,  xhi, xlo, nx4);
    split_kernel<<<nw4 / 256, 256>>>(Wq, wqhi, wqlo, nw4);
    split_kernel<<<nw4 / 256, 256>>>(Wk, wkhi, wklo, nw4);
    split_kernel<<<nw4 / 256, 256>>>(Wv, wvhi, wvlo, nw4);
    split_kernel<<<nw4 / 256, 256>>>(Wo, wohi, wolo, nw4);

    dim3 ggrid(D_MODEL / 128, M_TOT / 128);   // (8, 32)

    gemm_mma_kernel<1><<<ggrid, 256, GEMM_SMEM>>>(xhi, xlo, wqhi, wqlo, bq, nullptr);
    gemm_mma_kernel<2><<<ggrid, 256, GEMM_SMEM>>>(xhi, xlo, wkhi, wklo, bk, nullptr);
    gemm_mma_kernel<3><<<ggrid, 256, GEMM_SMEM>>>(xhi, xlo, wvhi, wvlo, bv, nullptr);

    attn_mma_kernel<<<dim3(SEQ / 128, N_HEADS, BATCH), 256, ATTN_SMEM>>>(mask);

    gemm_mma_kernel<0><<<ggrid, 256, GEMM_SMEM>>>(aohi, aolo, wohi, wolo, bo, out);
}

// round 5
// speedup vs baseline: 2.8988x; 1.0144x over previous
#include <cuda_runtime.h>
#include <cuda_bf16.h>
#include <math.h>
#include <stdint.h>

// Problem constants
#define D_MODEL   1024
#define N_HEADS   16
#define HEAD_DIM  64
#define SEQ       2048
#define BATCH     2
#define M_TOT     (BATCH * SEQ)      // 4096

// ---------------------------------------------------------------------------
// Scratch (device globals — no allocations allowed)
// ---------------------------------------------------------------------------
__device__ __align__(128) __nv_bfloat16 g_xhi [M_TOT * D_MODEL];
__device__ __align__(128) __nv_bfloat16 g_xlo [M_TOT * D_MODEL];
__device__ __align__(128) __nv_bfloat16 g_wqhi[D_MODEL * D_MODEL];
__device__ __align__(128) __nv_bfloat16 g_wqlo[D_MODEL * D_MODEL];
__device__ __align__(128) __nv_bfloat16 g_wkhi[D_MODEL * D_MODEL];
__device__ __align__(128) __nv_bfloat16 g_wklo[D_MODEL * D_MODEL];
__device__ __align__(128) __nv_bfloat16 g_wvhi[D_MODEL * D_MODEL];
__device__ __align__(128) __nv_bfloat16 g_wvlo[D_MODEL * D_MODEL];
__device__ __align__(128) __nv_bfloat16 g_wohi[D_MODEL * D_MODEL];
__device__ __align__(128) __nv_bfloat16 g_wolo[D_MODEL * D_MODEL];

#define QKV_ELEMS (BATCH * N_HEADS * SEQ * HEAD_DIM)
__device__ __align__(128) __nv_bfloat16 g_qhi[QKV_ELEMS];
__device__ __align__(128) __nv_bfloat16 g_qlo[QKV_ELEMS];
__device__ __align__(128) __nv_bfloat16 g_khi[QKV_ELEMS];
__device__ __align__(128) __nv_bfloat16 g_klo[QKV_ELEMS];
__device__ __align__(128) __nv_bfloat16 g_vhi[QKV_ELEMS];
__device__ __align__(128) __nv_bfloat16 g_vlo[QKV_ELEMS];

__device__ __align__(128) __nv_bfloat16 g_aohi[M_TOT * D_MODEL];
__device__ __align__(128) __nv_bfloat16 g_aolo[M_TOT * D_MODEL];

// ---------------------------------------------------------------------------
// Base-ISA helpers
// ---------------------------------------------------------------------------
__device__ __forceinline__ uint32_t smem_u32(const void* p) {
    uint32_t a;
    asm("{ .reg .u64 t; cvta.to.shared.u64 t, %1; cvt.u32.u64 %0, t; }"
        : "=r"(a) : "l"(p));
    return a;
}

__device__ __forceinline__ void ldsm_x4(uint32_t* r, uint32_t addr) {
    asm volatile("ldmatrix.sync.aligned.m8n8.x4.shared.b16 {%0,%1,%2,%3}, [%4];"
                 : "=r"(r[0]), "=r"(r[1]), "=r"(r[2]), "=r"(r[3]) : "r"(addr));
}
__device__ __forceinline__ void ldsm_x4_t(uint32_t* r, uint32_t addr) {
    asm volatile("ldmatrix.sync.aligned.m8n8.x4.trans.shared.b16 {%0,%1,%2,%3}, [%4];"
                 : "=r"(r[0]), "=r"(r[1]), "=r"(r[2]), "=r"(r[3]) : "r"(addr));
}

__device__ __forceinline__ void mma16816(float* c, const uint32_t* a,
                                         const uint32_t* b) {
    asm volatile(
        "mma.sync.aligned.m16n8k16.row.col.f32.bf16.bf16.f32 "
        "{%0,%1,%2,%3}, {%4,%5,%6,%7}, {%8,%9}, {%0,%1,%2,%3};"
        : "+f"(c[0]), "+f"(c[1]), "+f"(c[2]), "+f"(c[3])
        : "r"(a[0]), "r"(a[1]), "r"(a[2]), "r"(a[3]), "r"(b[0]), "r"(b[1]));
}

#define CP_ASYNC16(dst, src) \
    asm volatile("cp.async.cg.shared.global [%0], [%1], 16;" \
        :: "r"(dst), "l"(src))
#define CP_ASYNC4(dst, src) \
    asm volatile("cp.async.ca.shared.global [%0], [%1], 4;" \
        :: "r"(dst), "l"(src))
#define CP_COMMIT() asm volatile("cp.async.commit_group;" ::: "memory")
#define CP_WAIT1()  asm volatile("cp.async.wait_group 1;" ::: "memory")
#define CP_WAIT0()  asm volatile("cp.async.wait_group 0;" ::: "memory")

#define SWZ64(off)  ((off) ^ (((off) >> 3) & 0x30))
#define SWZ128(off) ((off) ^ (((off) >> 3) & 0x70))

__device__ __forceinline__ uint32_t packbf(__nv_bfloat16 lo, __nv_bfloat16 hi) {
    __nv_bfloat162 t = __halves2bfloat162(lo, hi);
    return *reinterpret_cast<uint32_t*>(&t);
}
__device__ __forceinline__ uint32_t split_pack_hi(float a, float b,
                                                  uint32_t& lop) {
    __nv_bfloat16 ha = __float2bfloat16(a);
    __nv_bfloat16 hb = __float2bfloat16(b);
    __nv_bfloat16 la = __float2bfloat16(a - __bfloat162float(ha));
    __nv_bfloat16 lb = __float2bfloat16(b - __bfloat162float(hb));
    lop = packbf(la, lb);
    return packbf(ha, hb);
}

// Q pre-scale: 1/sqrt(64) * log2(e)  (softmax uses exp2)
#define QSCALE (0.125f * 1.44269504088896f)

// ---------------------------------------------------------------------------
// fp32 -> bf16 hi/lo splits
// ---------------------------------------------------------------------------
__global__ void __launch_bounds__(256)
split_kernel(const float* __restrict__ src,
             __nv_bfloat16* __restrict__ hi,
             __nv_bfloat16* __restrict__ lo, int n4)
{
    int i = blockIdx.x * 256 + threadIdx.x;
    if (i >= n4) return;
    float4 v = reinterpret_cast<const float4*>(src)[i];
    __nv_bfloat16 h[4], l[4];
    float f[4] = {v.x, v.y, v.z, v.w};
    #pragma unroll
    for (int j = 0; j < 4; j++) {
        h[j] = __float2bfloat16(f[j]);
        l[j] = __float2bfloat16(f[j] - __bfloat162float(h[j]));
    }
    reinterpret_cast<uint2*>(hi)[i] = *reinterpret_cast<uint2*>(h);
    reinterpret_cast<uint2*>(lo)[i] = *reinterpret_cast<uint2*>(l);
}

// all four weight matrices in one launch (blockIdx.y selects)
__global__ void __launch_bounds__(256)
split4_kernel(const float* __restrict__ w0, const float* __restrict__ w1,
              const float* __restrict__ w2, const float* __restrict__ w3)
{
    const int y = blockIdx.y;
    const float* src = (y == 0) ? w0 : (y == 1) ? w1 : (y == 2) ? w2 : w3;
    __nv_bfloat16* hi = (y == 0) ? g_wqhi : (y == 1) ? g_wkhi
                       : (y == 2) ? g_wvhi : g_wohi;
    __nv_bfloat16* lo = (y == 0) ? g_wqlo : (y == 1) ? g_wklo
                       : (y == 2) ? g_wvlo : g_wolo;
    int i = blockIdx.x * 256 + threadIdx.x;
    float4 v = reinterpret_cast<const float4*>(src)[i];
    __nv_bfloat16 h[4], l[4];
    float f[4] = {v.x, v.y, v.z, v.w};
    #pragma unroll
    for (int j = 0; j < 4; j++) {
        h[j] = __float2bfloat16(f[j]);
        l[j] = __float2bfloat16(f[j] - __bfloat162float(h[j]));
    }
    reinterpret_cast<uint2*>(hi)[i] = *reinterpret_cast<uint2*>(h);
    reinterpret_cast<uint2*>(lo)[i] = *reinterpret_cast<uint2*>(l);
}

// ---------------------------------------------------------------------------
// GEMM core (3-stage cp.async pipeline, one __syncthreads per chunk)
// C[m,n] = sum_k A[m,k]*B[n,k] + bias[n];  D = Ahi*Bhi + Ahi*Blo + Alo*Bhi
// ---------------------------------------------------------------------------
#define ARR_B    8192
#define STAGE_B  (4 * ARR_B)          // 32 KB
#define GEMM_SMEM (3 * STAGE_B)       // 96 KB

// QKV = 1: blockIdx.z selects Wq/Wk/Wv + split-scatter epilogue.
// QKV = 0: single GEMM, fp32 row-major epilogue to C.
template <int QKV>
__global__ void __launch_bounds__(256, 2)
gemm_mma_kernel(const __nv_bfloat16* __restrict__ Ahi,
                const __nv_bfloat16* __restrict__ Alo,
                const __nv_bfloat16* __restrict__ Bhi0,
                const __nv_bfloat16* __restrict__ Blo0,
                const float* __restrict__ bias0,
                const __nv_bfloat16* __restrict__ Bhi1,
                const __nv_bfloat16* __restrict__ Blo1,
                const float* __restrict__ bias1,
                const __nv_bfloat16* __restrict__ Bhi2,
                const __nv_bfloat16* __restrict__ Blo2,
                const float* __restrict__ bias2,
                float* __restrict__ C)
{
    extern __shared__ char smem[];
    const uint32_t sbase = smem_u32(smem);
    const int tid  = threadIdx.x;
    const int lane = tid & 31;
    const int wid  = tid >> 5;
    const int bm = blockIdx.y * 128;
    const int bn = blockIdx.x * 128;
    const int z  = QKV ? blockIdx.z : 0;
    const int wm = (wid >> 2) * 64;
    const int wn = (wid & 3) * 32;

    const __nv_bfloat16* Bhi = Bhi0;
    const __nv_bfloat16* Blo = Blo0;
    const float* bias = bias0;
    if (QKV) {
        if (z == 1) { Bhi = Bhi1; Blo = Blo1; bias = bias1; }
        else if (z == 2) { Bhi = Bhi2; Blo = Blo2; bias = bias2; }
    }

    float acc[4][4][4];
    #pragma unroll
    for (int i = 0; i < 4; i++)
        #pragma unroll
        for (int j = 0; j < 4; j++)
            #pragma unroll
            for (int k = 0; k < 4; k++)
                acc[i][j][k] = 0.0f;

    const int r0 = tid >> 2;
    const int c0 = tid & 3;

    auto load_stage = [&](int s, int kc) {
        const uint32_t sb = sbase + s * STAGE_B;
        #pragma unroll
        for (int it = 0; it < 2; it++) {
            const int r = r0 + it * 64;
            const uint32_t so = SWZ64((uint32_t)(r * 64 + c0 * 16));
            const size_t ga = (size_t)(bm + r) * 1024 + kc + c0 * 8;
            const size_t gb = (size_t)(bn + r) * 1024 + kc + c0 * 8;
            CP_ASYNC16(sb + 0 * ARR_B + so, Ahi + ga);
            CP_ASYNC16(sb + 1 * ARR_B + so, Alo + ga);
            CP_ASYNC16(sb + 2 * ARR_B + so, Bhi + gb);
            CP_ASYNC16(sb + 3 * ARR_B + so, Blo + gb);
        }
    };

    load_stage(0, 0);
    CP_COMMIT();
    load_stage(1, 32);
    CP_COMMIT();

    const int lrow = lane & 15;
    const int lcolB = (lane >> 4) << 4;

    for (int c = 0; c < 32; c++) {
        CP_WAIT1();
        __syncthreads();
        if (c + 2 < 32) load_stage((c + 2) % 3, (c + 2) * 32);
        CP_COMMIT();

        const uint32_t sA   = sbase + (c % 3) * STAGE_B;
        const uint32_t sAlo = sA + ARR_B;
        const uint32_t sBhi = sA + 2 * ARR_B;
        const uint32_t sBlo = sA + 3 * ARR_B;

        #pragma unroll
        for (int kk = 0; kk < 2; kk++) {
            const int colB = kk * 32 + lcolB;

            uint32_t bhi[2][4], blo[2][4];
            #pragma unroll
            for (int p = 0; p < 2; p++) {
                const uint32_t off =
                    SWZ64((uint32_t)((wn + p * 16 + lrow) * 64 + colB));
                ldsm_x4(bhi[p], sBhi + off);
                ldsm_x4(blo[p], sBlo + off);
            }

            #pragma unroll
            for (int mt = 0; mt < 4; mt++) {
                const uint32_t off =
                    SWZ64((uint32_t)((wm + mt * 16 + lrow) * 64 + colB));
                uint32_t ahi[4], alo[4];
                ldsm_x4(ahi, sA + off);
                ldsm_x4(alo, sAlo + off);

                #pragma unroll
                for (int nt = 0; nt < 4; nt++) {
                    const int p = nt >> 1, sl = nt & 1;
                    uint32_t bh[2] = { bhi[p][sl], bhi[p][sl + 2] };
                    uint32_t bl[2] = { blo[p][sl], blo[p][sl + 2] };
                    mma16816(acc[mt][nt], ahi, bh);
                    mma16816(acc[mt][nt], ahi, bl);
                    mma16816(acc[mt][nt], alo, bh);
                }
            }
        }
    }

    const int gID = lane >> 2;
    const int tig = lane & 3;
    const float scale = (QKV && z == 0) ? QSCALE : 1.0f;
    __nv_bfloat16* dhi = (z == 0) ? g_qhi : (z == 1) ? g_khi : g_vhi;
    __nv_bfloat16* dlo = (z == 0) ? g_qlo : (z == 1) ? g_klo : g_vlo;

    #pragma unroll
    for (int mt = 0; mt < 4; mt++) {
        const int row0 = bm + wm + mt * 16 + gID;
        #pragma unroll
        for (int nt = 0; nt < 4; nt++) {
            const int col = bn + wn + nt * 8 + tig * 2;
            const float bb0 = bias[col];
            const float bb1 = bias[col + 1];
            #pragma unroll
            for (int half = 0; half < 2; half++) {
                const int m = row0 + half * 8;
                float vx = acc[mt][nt][half * 2 + 0] + bb0;
                float vy = acc[mt][nt][half * 2 + 1] + bb1;
                if (!QKV) {
                    *reinterpret_cast<float2*>(&C[(size_t)m * 1024 + col]) =
                        make_float2(vx, vy);
                } else {
                    vx *= scale; vy *= scale;
                    uint32_t lop;
                    const uint32_t hip = split_pack_hi(vx, vy, lop);
                    const int b = m >> 11, s = m & 2047;
                    const int hh = col >> 6, d = col & 63;
                    const size_t idx =
                        ((size_t)((b << 4) + hh) * SEQ + s) * HEAD_DIM + d;
                    *reinterpret_cast<uint32_t*>(&dhi[idx]) = hip;
                    *reinterpret_cast<uint32_t*>(&dlo[idx]) = lop;
                }
            }
        }
    }
}

// ---------------------------------------------------------------------------
// Flash attention: Q fragments register-resident, 3-stage cp.async KV
// pipeline, exp2-domain softmax (Q pre-scaled by log2e/8).
// smem: stage s (s=0..2) at s*32768: Khi(8K) Klo(8K) Vhi(8K) Vlo(8K);
// mask at 98304 + s*256.  Q staged through stage-0 region initially.
// ---------------------------------------------------------------------------
#define ATTN_SMEM 99072

__global__ void __launch_bounds__(256, 1)
attn_mma_kernel(const int* __restrict__ mask)
{
    extern __shared__ char smn[];
    const uint32_t sb = smem_u32(smn);
    const int tid  = threadIdx.x;
    const int lane = tid & 31;
    const int w    = tid >> 5;
    const int qb   = blockIdx.x;
    const int h    = blockIdx.y;
    const int b    = blockIdx.z;
    const int bh   = b * N_HEADS + h;
    const int g    = lane >> 2;
    const int tig  = lane & 3;
    const int lrow = lane & 15;
    const int lhi16 = (lane >> 4) & 1;

    const __nv_bfloat16* Qhi = g_qhi + ((size_t)bh * SEQ + qb * 128) * 64;
    const __nv_bfloat16* Qlo = g_qlo + ((size_t)bh * SEQ + qb * 128) * 64;
    const __nv_bfloat16* Khi = g_khi + (size_t)bh * SEQ * 64;
    const __nv_bfloat16* Klo = g_klo + (size_t)bh * SEQ * 64;
    const __nv_bfloat16* Vhi = g_vhi + (size_t)bh * SEQ * 64;
    const __nv_bfloat16* Vlo = g_vlo + (size_t)bh * SEQ * 64;
    const int* maskb = mask + (size_t)b * SEQ;

    // ---- stage Q through smem (stage-0 region), lift fragments to regs ----
    #pragma unroll
    for (int i = 0; i < 8; i++) {
        const int idx = i * 256 + tid;
        const int arr = idx >> 10;             // 0 hi, 1 lo
        const int rem = idx & 1023;
        const int r = rem >> 3, cc = rem & 7;
        const uint32_t dst =
            sb + arr * 16384 + SWZ128((uint32_t)(r * 128 + cc * 16));
        const __nv_bfloat16* src = (arr ? Qlo : Qhi) + r * 64 + cc * 8;
        CP_ASYNC16(dst, src);
    }
    CP_COMMIT();
    CP_WAIT0();
    __syncthreads();

    uint32_t qh[4][4], ql[4][4];
    #pragma unroll
    for (int ks = 0; ks < 4; ks++) {
        const uint32_t offq = SWZ128(
            (uint32_t)((w * 16 + lrow) * 128 + (ks * 16 + lhi16 * 8) * 2));
        ldsm_x4(qh[ks], sb + offq);
        ldsm_x4(ql[ks], sb + 16384 + offq);
    }
    __syncthreads();   // all warps done reading Q; smem free for KV stages

    auto load_kv = [&](int s, int t) {
        const uint32_t stb = sb + s * 32768;
        #pragma unroll
        for (int i = 0; i < 8; i++) {
            const int idx = i * 256 + tid;
            const int arr = idx >> 9;          // 0 khi,1 klo,2 vhi,3 vlo
            const int rem = idx & 511;
            const int r = rem >> 3, cc = rem & 7;
            const uint32_t dst =
                stb + arr * 8192 + SWZ128((uint32_t)(r * 128 + cc * 16));
            const __nv_bfloat16* base =
                (arr == 0) ? Khi : (arr == 1) ? Klo : (arr == 2) ? Vhi : Vlo;
            CP_ASYNC16(dst, base + (size_t)(t * 64 + r) * 64 + cc * 8);
        }
        if (tid < 64) {
            const uint32_t mdst = sb + 98304 + s * 256 + tid * 4;
            CP_ASYNC4(mdst, maskb + t * 64 + tid);
        }
    };

    load_kv(0, 0);
    CP_COMMIT();
    load_kv(1, 1);
    CP_COMMIT();

    float o[8][4];
    #pragma unroll
    for (int nt = 0; nt < 8; nt++)
        #pragma unroll
        for (int e = 0; e < 4; e++)
            o[nt][e] = 0.0f;
    float m0 = -INFINITY, m1 = -INFINITY, l0 = 0.0f, l1 = 0.0f;

    for (int t = 0; t < 32; t++) {
        CP_WAIT1();
        __syncthreads();
        if (t + 2 < 32) load_kv((t + 2) % 3, t + 2);
        CP_COMMIT();

        const int s = t % 3;
        const uint32_t sK   = sb + s * 32768;
        const uint32_t sKlo = sK + 8192;
        const uint32_t sV   = sK + 16384;
        const uint32_t sVlo = sK + 24576;

        // ---- S = Q K^T (3-term bf16), Q from registers ----
        float sacc[8][4];
        #pragma unroll
        for (int nt = 0; nt < 8; nt++)
            #pragma unroll
            for (int e = 0; e < 4; e++)
                sacc[nt][e] = 0.0f;

        #pragma unroll
        for (int ks = 0; ks < 4; ks++) {
            #pragma unroll
            for (int np = 0; np < 4; np++) {
                const uint32_t offk = SWZ128(
                    (uint32_t)((np * 16 + lrow) * 128 + (ks * 16 + lhi16 * 8) * 2));
                uint32_t kh[4], kl[4];
                ldsm_x4(kh, sK + offk);
                ldsm_x4(kl, sKlo + offk);
                uint32_t b0h[2] = {kh[0], kh[2]}, b0l[2] = {kl[0], kl[2]};
                uint32_t b1h[2] = {kh[1], kh[3]}, b1l[2] = {kl[1], kl[3]};
                mma16816(sacc[np * 2],     qh[ks], b0h);
                mma16816(sacc[np * 2],     qh[ks], b0l);
                mma16816(sacc[np * 2],     ql[ks], b0h);
                mma16816(sacc[np * 2 + 1], qh[ks], b1h);
                mma16816(sacc[np * 2 + 1], qh[ks], b1l);
                mma16816(sacc[np * 2 + 1], ql[ks], b1h);
            }
        }

        // ---- mask ----
        const int* mskp = (const int*)(smn + 98304 + s * 256);
        const int jb = tig * 2;
        #pragma unroll
        for (int nt = 0; nt < 8; nt++) {
            if (mskp[nt * 8 + jb] == 0) {
                sacc[nt][0] = -1.0e10f; sacc[nt][2] = -1.0e10f;
            }
            if (mskp[nt * 8 + jb + 1] == 0) {
                sacc[nt][1] = -1.0e10f; sacc[nt][3] = -1.0e10f;
            }
        }

        // ---- online softmax in exp2 domain ----
        float r0 = -INFINITY, r1 = -INFINITY;
        #pragma unroll
        for (int nt = 0; nt < 8; nt++) {
            r0 = fmaxf(r0, fmaxf(sacc[nt][0], sacc[nt][1]));
            r1 = fmaxf(r1, fmaxf(sacc[nt][2], sacc[nt][3]));
        }
        r0 = fmaxf(r0, __shfl_xor_sync(0xffffffffu, r0, 1));
        r0 = fmaxf(r0, __shfl_xor_sync(0xffffffffu, r0, 2));
        r1 = fmaxf(r1, __shfl_xor_sync(0xffffffffu, r1, 1));
        r1 = fmaxf(r1, __shfl_xor_sync(0xffffffffu, r1, 2));

        const float mn0 = fmaxf(m0, r0), mn1 = fmaxf(m1, r1);
        const float a0 = exp2f(m0 - mn0), a1 = exp2f(m1 - mn1);
        m0 = mn0; m1 = mn1;

        float ls0 = 0.0f, ls1 = 0.0f;
        #pragma unroll
        for (int nt = 0; nt < 8; nt++) {
            sacc[nt][0] = exp2f(sacc[nt][0] - mn0);
            sacc[nt][1] = exp2f(sacc[nt][1] - mn0);
            sacc[nt][2] = exp2f(sacc[nt][2] - mn1);
            sacc[nt][3] = exp2f(sacc[nt][3] - mn1);
            ls0 += sacc[nt][0] + sacc[nt][1];
            ls1 += sacc[nt][2] + sacc[nt][3];
            o[nt][0] *= a0; o[nt][1] *= a0;
            o[nt][2] *= a1; o[nt][3] *= a1;
        }
        l0 = l0 * a0 + ls0;
        l1 = l1 * a1 + ls1;

        // ---- P fragments (C-layout == A-layout identity) ----
        uint32_t pfh[4][4], pfl[4][4];
        #pragma unroll
        for (int ks = 0; ks < 4; ks++) {
            #pragma unroll
            for (int half = 0; half < 2; half++) {
                const int nt = 2 * ks + half;
                pfh[ks][half * 2 + 0] =
                    split_pack_hi(sacc[nt][0], sacc[nt][1], pfl[ks][half * 2 + 0]);
                pfh[ks][half * 2 + 1] =
                    split_pack_hi(sacc[nt][2], sacc[nt][3], pfl[ks][half * 2 + 1]);
            }
        }

        // ---- O += P V (3-term; V^T via ldmatrix.trans) ----
        #pragma unroll
        for (int ks = 0; ks < 4; ks++) {
            #pragma unroll
            for (int np = 0; np < 4; np++) {
                const uint32_t offv = SWZ128(
                    (uint32_t)((ks * 16 + lrow) * 128 + (np * 16 + lhi16 * 8) * 2));
                uint32_t vh[4], vl[4];
                ldsm_x4_t(vh, sV + offv);
                ldsm_x4_t(vl, sVlo + offv);
                uint32_t b0h[2] = {vh[0], vh[1]}, b0l[2] = {vl[0], vl[1]};
                uint32_t b1h[2] = {vh[2], vh[3]}, b1l[2] = {vl[2], vl[3]};
                mma16816(o[np * 2],     pfh[ks], b0h);
                mma16816(o[np * 2],     pfh[ks], b0l);
                mma16816(o[np * 2],     pfl[ks], b0h);
                mma16816(o[np * 2 + 1], pfh[ks], b1h);
                mma16816(o[np * 2 + 1], pfh[ks], b1l);
                mma16816(o[np * 2 + 1], pfl[ks], b1h);
            }
        }
    }

    // ---- finalize ----
    l0 += __shfl_xor_sync(0xffffffffu, l0, 1);
    l0 += __shfl_xor_sync(0xffffffffu, l0, 2);
    l1 += __shfl_xor_sync(0xffffffffu, l1, 1);
    l1 += __shfl_xor_sync(0xffffffffu, l1, 2);
    const float inv0 = 1.0f / l0;
    const float inv1 = 1.0f / l1;

    const int row0 = qb * 128 + w * 16 + g;
    #pragma unroll
    for (int nt = 0; nt < 8; nt++) {
        const int col = h * 64 + nt * 8 + tig * 2;
        uint32_t lop;
        uint32_t hip = split_pack_hi(o[nt][0] * inv0, o[nt][1] * inv0, lop);
        size_t idx = ((size_t)b * SEQ + row0) * D_MODEL + col;
        *reinterpret_cast<uint32_t*>(&g_aohi[idx]) = hip;
        *reinterpret_cast<uint32_t*>(&g_aolo[idx]) = lop;

        hip = split_pack_hi(o[nt][2] * inv1, o[nt][3] * inv1, lop);
        idx = ((size_t)b * SEQ + row0 + 8) * D_MODEL + col;
        *reinterpret_cast<uint32_t*>(&g_aohi[idx]) = hip;
        *reinterpret_cast<uint32_t*>(&g_aolo[idx]) = lop;
    }
}

// ---------------------------------------------------------------------------
// Launcher
// ---------------------------------------------------------------------------
extern "C" void kernel_launch(void* const* d_in, const int* in_sizes, int n_in,
                              void* d_out, int out_size)
{
    const float* x    = (const float*)d_in[0];
    const int*   mask = (const int*)  d_in[1];
    const float* Wq   = (const float*)d_in[2];
    const float* bq   = (const float*)d_in[3];
    const float* Wk   = (const float*)d_in[4];
    const float* bk   = (const float*)d_in[5];
    const float* Wv   = (const float*)d_in[6];
    const float* bv   = (const float*)d_in[7];
    const float* Wo   = (const float*)d_in[8];
    const float* bo   = (const float*)d_in[9];
    float* out = (float*)d_out;

    __nv_bfloat16 *xhi, *xlo, *aohi, *aolo;
    __nv_bfloat16 *wqhi, *wqlo, *wkhi, *wklo, *wvhi, *wvlo, *wohi, *wolo;
    cudaGetSymbolAddress((void**)&xhi,  g_xhi);
    cudaGetSymbolAddress((void**)&xlo,  g_xlo);
    cudaGetSymbolAddress((void**)&aohi, g_aohi);
    cudaGetSymbolAddress((void**)&aolo, g_aolo);
    cudaGetSymbolAddress((void**)&wqhi, g_wqhi);
    cudaGetSymbolAddress((void**)&wqlo, g_wqlo);
    cudaGetSymbolAddress((void**)&wkhi, g_wkhi);
    cudaGetSymbolAddress((void**)&wklo, g_wklo);
    cudaGetSymbolAddress((void**)&wvhi, g_wvhi);
    cudaGetSymbolAddress((void**)&wvlo, g_wvlo);
    cudaGetSymbolAddress((void**)&wohi, g_wohi);
    cudaGetSymbolAddress((void**)&wolo, g_wolo);

    cudaFuncSetAttribute(gemm_mma_kernel<0>, cudaFuncAttributeMaxDynamicSharedMemorySize, GEMM_SMEM);
    cudaFuncSetAttribute(gemm_mma_kernel<1>, cudaFuncAttributeMaxDynamicSharedMemorySize, GEMM_SMEM);
    cudaFuncSetAttribute(attn_mma_kernel,    cudaFuncAttributeMaxDynamicSharedMemorySize, ATTN_SMEM);

    const int nx4 = M_TOT * D_MODEL / 4;      // 1048576
    const int nw4 = D_MODEL * D_MODEL / 4;    // 262144

    split_kernel<<<nx4 / 256, 256>>>(x, xhi, xlo, nx4);
    split4_kernel<<<dim3(nw4 / 256, 4), 256>>>(Wq, Wk, Wv, Wo);

    dim3 qkvgrid(D_MODEL / 128, M_TOT / 128, 3);   // (8, 32, 3)
    gemm_mma_kernel<1><<<qkvgrid, 256, GEMM_SMEM>>>(
        xhi, xlo,
        wqhi, wqlo, bq,
        wkhi, wklo, bk,
        wvhi, wvlo, bv,
        nullptr);

    attn_mma_kernel<<<dim3(SEQ / 128, N_HEADS, BATCH), 256, ATTN_SMEM>>>(mask);

    dim3 ogrid(D_MODEL / 128, M_TOT / 128, 1);
    gemm_mma_kernel<0><<<ogrid, 256, GEMM_SMEM>>>(
        aohi, aolo,
        wohi, wolo, bo,
        nullptr, nullptr, nullptr,
        nullptr, nullptr, nullptr,
        out);
}